// round 1
// baseline (speedup 1.0000x reference)
#include <cuda_runtime.h>

// Problem constants
#define NV_   4096   // concept embeddings
#define B_    8      // batch
#define ND_   512    // tokens per batch row
#define NODES_ 512   // phi_vs node_num
#define D_    128    // embedding dim (= GEMM K)

// f32 bin geometry, matching jnp.linspace(-0.5, 0.99, 15) computed in f32:
// step = fl(fl(0.99 - (-0.5)) / 14)
#define STEPF   ((0.99f - (-0.5f)) / 14.0f)
#define INV_STEP 9.3959731543624161f   // 14/1.49 in double, rounded

// Scratch (allocation-free rule: __device__ globals)
__device__ float g_a[B_ * NV_];
__device__ float g_binw[16];
__device__ int   g_is64;

// ---------------------------------------------------------------------------
// Kernel 0: zero the a-accumulator, compute bin weights (start + cumsum(relu)),
//           and sniff doc_index dtype (int64 vs int32 under JAX x64-off).
// ---------------------------------------------------------------------------
__global__ void k0_init(const float* __restrict__ diff,
                        const float* __restrict__ start,
                        const void* __restrict__ doc) {
    int tid = blockIdx.x * blockDim.x + threadIdx.x;
    int stride = gridDim.x * blockDim.x;
    for (int i = tid; i < B_ * NV_; i += stride) g_a[i] = 0.0f;
    if (tid == 0) {
        float s0 = start[0];
        float acc = 0.0f;
        for (int i = 0; i < 16; i++) {
            float d = diff[i];
            acc += (d > 0.0f) ? d : 0.0f;
            g_binw[i] = s0 + acc;
        }
        // dtype sniff: if doc is int32, reading as int64 pairs low+hi words ->
        // values ~ hi*2^32 (hi is a random index in [0,50001), ~never 0 four times).
        const long long* p64 = (const long long*)doc;
        int ok = 1;
        for (int i = 0; i < 4; i++) {
            long long v = p64[i];
            if (v < 0 || v >= 50001LL) ok = 0;
        }
        g_is64 = ok;
    }
}

// ---------------------------------------------------------------------------
// Kernel 1: fused GEMM (sim = E[doc] @ VvT) + digitize + bin lookup +
//           attn-weighted reduction over token rows -> atomicAdd into g_a.
// Tile: 128(M) x 128(N) x 128(K=full), 256 threads, 8x8 micro-tile per thread
// in 2x2 quadrants (rows ty*4..+3 and 64+ty*4..+3; cols likewise by tx).
// ---------------------------------------------------------------------------
__global__ void __launch_bounds__(256, 1)
k1_gemm(const void* __restrict__ doc_raw,
        const float* __restrict__ attn,
        const float* __restrict__ emb,
        const float* __restrict__ vvt) {
    extern __shared__ float sm[];
    float* As     = sm;                    // [k][m], stride 132 (float4-aligned rows)
    float* Bs     = sm + 128 * 132;        // [k][n], stride 128
    float* attn_s = Bs + 128 * 128;        // 128
    float* binw_s = attn_s + 128;          // 16

    const int tid   = threadIdx.x;
    const int mbase = blockIdx.y * 128;
    const int nbase = blockIdx.x * 128;
    const int is64  = g_is64;

    if (tid < 128) attn_s[tid] = attn[mbase + tid];
    if (tid >= 128 && tid < 144) binw_s[tid - 128] = g_binw[tid - 128];

    // --- load A (gather + transpose to [k][m]); lanes map to rows so the
    //     scalar STS is consecutive-address = conflict-free ---
    {
        const long long* doc64 = (const long long*)doc_raw;
        const int*       doc32 = (const int*)doc_raw;
        const float4* emb4 = (const float4*)emb;
        int rl = tid & 31;    // row within 32-group
        int kq = tid >> 5;    // 0..7
        #pragma unroll
        for (int it = 0; it < 16; it++) {
            int r   = rl + 32 * (it & 3);
            int kf4 = kq + 8 * (it >> 2);         // float4 index over k: 0..31
            long long idx = is64 ? doc64[mbase + r] : (long long)doc32[mbase + r];
            float4 v = emb4[idx * 32 + kf4];
            int kk = kf4 * 4;
            As[(kk + 0) * 132 + r] = v.x;
            As[(kk + 1) * 132 + r] = v.y;
            As[(kk + 2) * 132 + r] = v.z;
            As[(kk + 3) * 132 + r] = v.w;
        }
    }
    // --- load B tile (coalesced, conflict-free float4 STS) ---
    {
        const float4* vvt4 = (const float4*)vvt;
        float4* Bs4 = (float4*)Bs;
        int n4 = tid & 31;
        int kb = tid >> 5;
        #pragma unroll
        for (int it = 0; it < 16; it++) {
            int k = kb + 8 * it;
            Bs4[k * 32 + n4] = vvt4[(size_t)k * (NV_ / 4) + (nbase >> 2) + n4];
        }
    }
    __syncthreads();

    const int tx = tid & 15;
    const int ty = tid >> 4;
    float acc[8][8];
    #pragma unroll
    for (int i = 0; i < 8; i++)
        #pragma unroll
        for (int j = 0; j < 8; j++) acc[i][j] = 0.0f;

    #pragma unroll 4
    for (int k = 0; k < 128; k++) {
        float4 a0 = *(const float4*)&As[k * 132 + ty * 4];
        float4 a1 = *(const float4*)&As[k * 132 + 64 + ty * 4];
        float4 b0 = *(const float4*)&Bs[k * 128 + tx * 4];
        float4 b1 = *(const float4*)&Bs[k * 128 + 64 + tx * 4];
        float ar[8] = {a0.x, a0.y, a0.z, a0.w, a1.x, a1.y, a1.z, a1.w};
        float br[8] = {b0.x, b0.y, b0.z, b0.w, b1.x, b1.y, b1.z, b1.w};
        #pragma unroll
        for (int i = 0; i < 8; i++)
            #pragma unroll
            for (int j = 0; j < 8; j++)
                acc[i][j] = fmaf(ar[i], br[j], acc[i][j]);
    }

    // --- epilogue: digitize (exact np.digitize semantics via arithmetic
    //     estimate + +/-1 correction against f32 linspace boundaries),
    //     bin-weight lookup, attn-weighted row reduction ---
    float p[8];
    #pragma unroll
    for (int c = 0; c < 8; c++) p[c] = 0.0f;

    #pragma unroll
    for (int i = 0; i < 8; i++) {
        int r = (i < 4) ? (ty * 4 + i) : (64 + ty * 4 + (i - 4));
        float av = attn_s[r];
        #pragma unroll
        for (int c = 0; c < 8; c++) {
            float s = acc[i][c];
            float t = (s + 0.5f) * INV_STEP;
            int d = (int)floorf(t) + 1;
            d = d < 0 ? 0 : (d > 15 ? 15 : d);
            // exact correction: boundary b_k = -0.5f + k*STEPF (f32 ops)
            float bd = -0.5f + (float)d * STEPF;
            if (d < 15 && s >= bd) d++;
            float bdm = -0.5f + (float)(d - 1) * STEPF;
            if (d > 0 && s < bdm) d--;
            p[c] = fmaf(av, binw_s[d], p[c]);
        }
    }

    __syncthreads();           // done reading As; reuse as reduction buffer
    float* red = sm;           // [16][128]
    #pragma unroll
    for (int c = 0; c < 8; c++) {
        int col = (c < 4) ? (tx * 4 + c) : (64 + tx * 4 + (c - 4));
        red[ty * 128 + col] = p[c];
    }
    __syncthreads();
    #pragma unroll
    for (int off = 8; off > 0; off >>= 1) {
        if (ty < off) {
            #pragma unroll
            for (int c = 0; c < 8; c++) {
                int col = (c < 4) ? (tx * 4 + c) : (64 + tx * 4 + (c - 4));
                red[ty * 128 + col] += red[(ty + off) * 128 + col];
            }
        }
        __syncthreads();
    }
    if (ty == 0) {
        int bb = mbase >> 9;   // 512 rows per batch element
        #pragma unroll
        for (int c = 0; c < 8; c++) {
            int col = (c < 4) ? (tx * 4 + c) : (64 + tx * 4 + (c - 4));
            atomicAdd(&g_a[bb * NV_ + nbase + col], red[col]);
        }
    }
}

// ---------------------------------------------------------------------------
// Kernel 2: final[b,j] = sum_v a[b,v] * phi[j,v].  One warp per output,
// coalesced float4 strided reads, warp shuffle reduction. phi is L2-resident.
// ---------------------------------------------------------------------------
__global__ void __launch_bounds__(256)
k2_final(const float* __restrict__ phi, float* __restrict__ out) {
    int wid = threadIdx.x >> 5, lane = threadIdx.x & 31;
    int g = blockIdx.x * 8 + wid;      // 0..4095
    int b = g & 7, j = g >> 3;
    const float4* pa = (const float4*)(g_a + b * NV_);
    const float4* pp = (const float4*)(phi + (size_t)j * NV_);
    float acc = 0.0f;
    #pragma unroll
    for (int i = 0; i < 32; i++) {
        float4 va = pa[i * 32 + lane];
        float4 vp = pp[i * 32 + lane];
        acc = fmaf(va.x, vp.x, acc);
        acc = fmaf(va.y, vp.y, acc);
        acc = fmaf(va.z, vp.z, acc);
        acc = fmaf(va.w, vp.w, acc);
    }
    #pragma unroll
    for (int off = 16; off > 0; off >>= 1)
        acc += __shfl_xor_sync(0xffffffffu, acc, off);
    if (lane == 0) out[b * NODES_ + j] = acc;
}

// ---------------------------------------------------------------------------
extern "C" void kernel_launch(void* const* d_in, const int* in_sizes, int n_in,
                              void* d_out, int out_size) {
    const void*  doc   = d_in[0];                   // int64 or int32 (sniffed)
    const float* attn  = (const float*)d_in[1];     // [8,512]
    const float* emb   = (const float*)d_in[2];     // [50001,128]
    const float* vvt   = (const float*)d_in[3];     // [128,4096]
    const float* phi   = (const float*)d_in[4];     // [512,4096]
    const float* diff  = (const float*)d_in[5];     // [16]
    const float* start = (const float*)d_in[6];     // [1]
    float* out = (float*)d_out;                     // [8,512] f32

    size_t smem = (size_t)(128 * 132 + 128 * 128 + 128 + 16) * sizeof(float);
    cudaFuncSetAttribute(k1_gemm, cudaFuncAttributeMaxDynamicSharedMemorySize,
                         (int)smem);

    k0_init<<<32, 256>>>(diff, start, doc);
    dim3 grid(NV_ / 128, (B_ * ND_) / 128);   // 32 x 32
    k1_gemm<<<grid, 256, smem>>>(doc, attn, emb, vvt);
    k2_final<<<(B_ * NODES_) / 8, 256>>>(phi, out);
}